// round 10
// baseline (speedup 1.0000x reference)
#include <cuda_runtime.h>
#include <math.h>

#define NN   1024            // nodes
#define NE   (32 * NN)       // edges
#define CI   8               // in channels
#define NM1  1023
#define PP   (NN * NM1)      // pairs
#define PAIRS_PER_BLK 512
#define NBLK_PAIRS (PP / PAIRS_PER_BLK)   // 2046
#define PRE_BLOCKS 128       // <= SM count: all co-resident, grid barrier safe

// ---- scratch (device globals; zero-init at load; re-zeroed by k_pairs tail) ----
__device__ float g_deg_out[NN];
__device__ float g_deg_in[NN];
__device__ float g_pfx[NN * CI];
__device__ float g_pbx[NN * CI];
__device__ float g_A[NN * 5];   // per-node w1-contribution via out[ii] slot, b1 FOLDED IN
__device__ float g_B[NN * 5];   // per-node w1-contribution via out[jj] slot

// grid-barrier state (returns to 0 after each launch -> replay deterministic)
__device__ unsigned g_count;
__device__ volatile unsigned g_sense;

// Sense-reversal grid barrier. ALL threads fence BEFORE the block arrives, so
// every thread's RED/atomic effects are published before the release.
__device__ __forceinline__ void grid_bar(unsigned& sense) {
    __threadfence();                           // publish this thread's writes
    __syncthreads();                           // whole block has fenced
    sense ^= 1u;
    if (threadIdx.x == 0) {
        if (atomicAdd(&g_count, 1u) == gridDim.x - 1) {
            g_count = 0;
            __threadfence();
            g_sense = sense;                   // release
        } else {
            while (g_sense != sense) __nanosleep(32);
        }
    }
    __syncthreads();
}

// vectorized global float4 reduction (sm_90+)
__device__ __forceinline__ void red4(float* p, float a, float b, float c, float d) {
    asm volatile("red.global.add.v4.f32 [%0], {%1,%2,%3,%4};"
                 :: "l"(p), "f"(a), "f"(b), "f"(c), "f"(d) : "memory");
}

// ---------------------------------------------------------------- fused pre-pass
// ONE kernel, 128 blocks x 256 threads (exactly 1 edge/thread), 3 phases with
// grid barriers:
//   A: degree atomics              B: edge aggregation (red4)
//   C: per-node GRU + A/B tables (warp per node, 8 nodes/block)
// Node weights are staged into smem during A/B (independent of edge results).
// Cross-phase accumulator reads use __ldcg (L2) — immune to stale L1.
__global__ void __launch_bounds__(256)
k_pre(const int* __restrict__ ei, const float* __restrict__ ew,
      const float* __restrict__ x,
      const float* __restrict__ Wz, const float* __restrict__ bz,
      const float* __restrict__ Wh, const float* __restrict__ bh,
      const float* __restrict__ w1, const float* __restrict__ b1) {
    __shared__ float swz0[8][32], swz1[8][32], swz2[8][32];
    __shared__ float swh0[8][32], swh1[8][32], swh2[8][32];
    __shared__ float sw1s[80][5];
    __shared__ float so[8][33];

    const int t = threadIdx.x;
    const int e = blockIdx.x * 256 + t;        // NE == PRE_BLOCKS*256 exactly
    const int r = ei[e];
    const int c = ei[NE + e];
    const float we = ew[e];
    unsigned sense = 0;

    // phase A: degrees -------------------------------------------------
    atomicAdd(&g_deg_out[r], we);
    atomicAdd(&g_deg_in[c], we);

    // stage node weights while atomics drain (independent work)
    {
        int k = t >> 5, ch = t & 31, o = k * 32 + ch;   // t covers all 256 slots
        swz0[k][ch] = __ldg(Wz + o) + __ldg(Wz + 2560 + o);
        swz1[k][ch] = __ldg(Wz + 1280 + o);
        swz2[k][ch] = __ldg(Wz + 3840 + o);
        swh0[k][ch] = __ldg(Wh + o) + __ldg(Wh + 2560 + o);
        swh1[k][ch] = __ldg(Wh + 1280 + o);
        swh2[k][ch] = __ldg(Wh + 3840 + o);
    }
    for (int idx = t; idx < 400; idx += 256)
        sw1s[idx / 5][idx % 5] = __ldg(w1 + idx);

    grid_bar(sense);

    // phase B: edge aggregation ---------------------------------------
    // (reference indexes deg_in by ROW — quirk kept)
    {
        float inv_do = __fdividef(1.f, __ldcg(&g_deg_out[r]));
        float inv_di = __fdividef(1.f, __ldcg(&g_deg_in[r]));
        const float4* xr = (const float4*)(x + r * 8);
        const float4* xc = (const float4*)(x + c * 8);
        float4 a0 = xr[0], a1 = xr[1];
        float4 b0 = xc[0], b1v = xc[1];
        red4(&g_pfx[c * 8],     inv_do * a0.x, inv_do * a0.y, inv_do * a0.z, inv_do * a0.w);
        red4(&g_pfx[c * 8 + 4], inv_do * a1.x, inv_do * a1.y, inv_do * a1.z, inv_do * a1.w);
        red4(&g_pbx[r * 8],     inv_di * b0.x, inv_di * b0.y, inv_di * b0.z, inv_di * b0.w);
        red4(&g_pbx[r * 8 + 4], inv_di * b1v.x, inv_di * b1v.y, inv_di * b1v.z, inv_di * b1v.w);
    }

    grid_bar(sense);

    // phase C: per-node GRU + A/B (warp per node) ---------------------
    {
        int wid = t >> 5, lane = t & 31;
        int n = blockIdx.x * 8 + wid;
        const int ch = lane;

        float xv[8], pf[8], pb[8];
#pragma unroll
        for (int k = 0; k < 8; k++) {
            xv[k] = __ldg(x + n * 8 + k);
            pf[k] = __ldcg(&g_pfx[n * 8 + k]);
            pb[k] = __ldcg(&g_pbx[n * 8 + k]);
        }

        float z = __ldg(bz + ch);
        float h = __ldg(bh + ch);
#pragma unroll
        for (int k = 0; k < 8; k++) {
            z += xv[k] * swz0[k][ch] + pf[k] * swz1[k][ch] + pb[k] * swz2[k][ch];
            h += xv[k] * swh0[k][ch] + pf[k] * swh1[k][ch] + pb[k] * swh2[k][ch];
        }
        float sig = 1.f / (1.f + __expf(-z));
        float Hn  = (1.f - sig) * tanhf(h);
        so[wid][ch] = fmaxf(Hn, 0.f);
        __syncwarp();

        if (lane < 10) {
            int half = lane / 5;       // 0 -> A (w1 rows 0..39), 1 -> B (rows 40..79)
            int m    = lane - half * 5;
            int base = half * 40;
            float acc = (half == 0) ? __ldg(b1 + m) : 0.f;   // fold b1 into A
#pragma unroll
            for (int cc = 0; cc < 32; cc++)
                acc += so[wid][cc] * sw1s[base + cc][m];
#pragma unroll
            for (int k = 0; k < 8; k++)
                acc += xv[k] * sw1s[base + 32 + k][m];
            if (half == 0) g_A[n * 5 + m] = acc;
            else           g_B[n * 5 + m] = acc;
        }
    }
}

// ---------------------------------------------------------------- pair MLP
// 512 threads x 1 pair. Weights packed in float4 smem rows (broadcast LDS.128),
// B rows staged in a circular 514-row window (stride-5, conflict-free).
__global__ void __launch_bounds__(512)
k_pairs(const float* __restrict__ dist, const float* __restrict__ lags,
        const float* __restrict__ lz_,  const float* __restrict__ a2d,
        const float* __restrict__ a2o,  const float* __restrict__ d2a,
        const float* __restrict__ o2a,  const float* __restrict__ vr,
        const float* __restrict__ w1,   const float* __restrict__ w2,
        const float* __restrict__ b2,   const float* __restrict__ w3,
        const float* __restrict__ b3,   const float* __restrict__ w4,
        const float* __restrict__ b4,   float* __restrict__ out) {
    __shared__ float4 sW1[5][3];   // [m]: {wd,wd2,wlg,wz0} {wtd,wto,wda,woa} {wvv,-,-,-}
    __shared__ float4 sW2[3][2];   // [q]: {m0..m3}, {m4, b2q, -, -}
    __shared__ float4 sW3v;        // {w3[0], w3[1], w3[2], b3}
    __shared__ float4 sW4v;        // {w4[0], w4[0]+w4[1], b4, -}
    __shared__ float  sA5[2][5];
    __shared__ float  sB[514 * 5];

    const int pblk = blockIdx.x * PAIRS_PER_BLK;
    const int i0   = pblk / NM1;
    const int kb   = pblk - i0 * NM1;
    int t = threadIdx.x;
    const int p = pblk + t;

    // ---- issue stream loads immediately (overlap DRAM latency with staging) ----
    float d  = __ldg(dist + p);
    float lg = __ldg(lags + p);
    float z0 = __ldg(lz_  + p);
    float td = __ldg(a2d  + p);
    float to = __ldg(a2o  + p);
    float da = __ldg(d2a  + p);
    float oa = __ldg(o2a  + p);
    float vv = __ldg(vr   + p);

    // tail-zero scratch for next launch (dead by this point): 18432 floats
    {
        int zi = blockIdx.x * blockDim.x + t;
        if (zi < NN / 2) ((float2*)g_deg_out)[zi] = make_float2(0.f, 0.f);
        else if (zi < NN) ((float2*)g_deg_in)[zi - NN / 2] = make_float2(0.f, 0.f);
        else if (zi < NN + NN * CI / 4)
            ((float4*)g_pfx)[zi - NN] = make_float4(0.f, 0.f, 0.f, 0.f);
        else if (zi < NN + NN * CI / 2)
            ((float4*)g_pbx)[zi - NN - NN * CI / 4] = make_float4(0.f, 0.f, 0.f, 0.f);
    }

    // stage packed weights
    if (t < 15) {                              // sW1: m = t/3, part = t%3
        int m = t / 3, part = t - m * 3;
        int f = part * 4;
        float a0 = w1[400 + f * 5 + m];
        float a1 = (part < 2) ? w1[400 + (f + 1) * 5 + m] : 0.f;
        float a2 = (part < 2) ? w1[400 + (f + 2) * 5 + m] : 0.f;
        float a3 = (part < 2) ? w1[400 + (f + 3) * 5 + m] : 0.f;
        sW1[m][part] = make_float4(a0, a1, a2, a3);
    } else if (t < 21) {                       // sW2: q = (t-15)/2, part = (t-15)%2
        int idx = t - 15, q = idx / 2, part = idx - q * 2;
        if (part == 0)
            sW2[q][0] = make_float4(w2[0 * 3 + q], w2[1 * 3 + q], w2[2 * 3 + q], w2[3 * 3 + q]);
        else
            sW2[q][1] = make_float4(w2[4 * 3 + q], b2[q], 0.f, 0.f);
    } else if (t == 21) {
        sW3v = make_float4(w3[0], w3[1], w3[2], b3[0]);
    } else if (t == 22) {
        float a = w4[0];
        sW4v = make_float4(a, a + w4[1], b4[0], 0.f);
    } else if (t >= 32 && t < 42) {            // stage A rows i0, i0+1 (b1 folded in)
        int q = t - 32, ia = q / 5, m = q - ia * 5;
        int row = min(i0 + ia, NN - 1);
        sA5[ia][m] = g_A[row * 5 + m];
    }
    // stage B circular window: row (kb + s) & 1023, s = 0..513
    for (int s = t; s < 514; s += 512) {
        int row = (kb + s) & (NN - 1);
#pragma unroll
        for (int m = 0; m < 5; m++) sB[s * 5 + m] = g_B[row * 5 + m];
    }
    __syncthreads();

    // i, k for this pair (single wrap possible within a block)
    int k = kb + t;
    int i = i0;
    if (k >= NM1) { k -= NM1; i = i0 + 1; }

    int j  = (k < i) ? k : (k + 1);
    int tw = (j - kb) & (NN - 1);              // circular window index, < 514
    const float* Bp = sB + tw * 5;
    const float* Ap = sA5[i - i0];
    float d2 = d * d;

    float h1[5];
#pragma unroll
    for (int m = 0; m < 5; m++) {
        float4 wa = sW1[m][0], wb = sW1[m][1], wc = sW1[m][2];
        float v = Ap[m] + Bp[m];
        v += d  * wa.x + d2 * wa.y + lg * wa.z + z0 * wa.w;
        v += td * wb.x + to * wb.y + da * wb.z + oa * wb.w;
        v += vv * wc.x;
        h1[m] = fmaxf(v, 0.f);
    }
    float h2[3];
#pragma unroll
    for (int q = 0; q < 3; q++) {
        float4 u = sW2[q][0], u2 = sW2[q][1];
        float v = u2.y + h1[0] * u.x + h1[1] * u.y + h1[2] * u.z + h1[3] * u.w + h1[4] * u2.x;
        h2[q] = fmaxf(v, 0.f);
    }
    float4 w3v = sW3v;
    float h3 = w3v.w + h2[0] * w3v.x + h2[1] * w3v.y + h2[2] * w3v.z;
    float4 w4v = sW4v;
    // lag_zeros is exactly 0.0 or 1.0 (round of uniform)
    float w4eff = (z0 != 0.f) ? w4v.y : w4v.x;
    out[p] = h3 * w4eff + w4v.z;
}

// ---------------------------------------------------------------- launch
extern "C" void kernel_launch(void* const* d_in, const int* in_sizes, int n_in,
                              void* d_out, int out_size) {
    const float* x    = (const float*)d_in[0];
    const int*   ei   = (const int*)  d_in[1];
    const float* ew   = (const float*)d_in[2];
    const float* dist = (const float*)d_in[3];
    const float* lags = (const float*)d_in[4];
    const float* lz   = (const float*)d_in[5];
    const float* a2d  = (const float*)d_in[6];
    const float* a2o  = (const float*)d_in[7];
    const float* d2a  = (const float*)d_in[8];
    const float* o2a  = (const float*)d_in[9];
    const float* vr   = (const float*)d_in[10];
    const float* Wz   = (const float*)d_in[11];
    const float* bz   = (const float*)d_in[12];
    // d_in[13], d_in[14] = Wr, br — dead (H0 == 0 makes the reset gate a no-op)
    const float* Wh   = (const float*)d_in[15];
    const float* bh   = (const float*)d_in[16];
    const float* w1   = (const float*)d_in[17];
    const float* b1   = (const float*)d_in[18];
    const float* w2   = (const float*)d_in[19];
    const float* b2   = (const float*)d_in[20];
    const float* w3   = (const float*)d_in[21];
    const float* b3   = (const float*)d_in[22];
    const float* w4   = (const float*)d_in[23];
    const float* b4   = (const float*)d_in[24];
    float* out = (float*)d_out;

    k_pre<<<PRE_BLOCKS, 256>>>(ei, ew, x, Wz, bz, Wh, bh, w1, b1);
    k_pairs<<<NBLK_PAIRS, 512>>>(dist, lags, lz, a2d, a2o, d2a, o2a, vr,
                                 w1, w2, b2, w3, b3, w4, b4, out);
}

// round 11
// speedup vs baseline: 1.2326x; 1.2326x over previous
#include <cuda_runtime.h>
#include <math.h>

#define NN   1024            // nodes
#define NE   (32 * NN)       // edges
#define CI   8               // in channels
#define NM1  1023
#define PP   (NN * NM1)      // pairs
#define PAIRS_PER_BLK 1024
#define NBLK_PAIRS (PP / PAIRS_PER_BLK)   // 1023

// ---- scratch (device globals; zero-init at load; re-zeroed by k_pairs tail) ----
__device__ float g_deg_out[NN];
__device__ float g_deg_in[NN];
__device__ float g_pfx[NN * CI];
__device__ float g_pbx[NN * CI];
__device__ __align__(16) float g_A[NN * 5];   // w1-contribution via out[ii], b1 FOLDED IN
__device__ __align__(16) float g_B[NN * 5];   // w1-contribution via out[jj]

// vectorized global float4 reduction (sm_90+)
__device__ __forceinline__ void red4(float* p, float a, float b, float c, float d) {
    asm volatile("red.global.add.v4.f32 [%0], {%1,%2,%3,%4};"
                 :: "l"(p), "f"(a), "f"(b), "f"(c), "f"(d) : "memory");
}

// ---------------------------------------------------------------- degrees
__global__ void k_deg(const int* __restrict__ ei, const float* __restrict__ w) {
    int e = blockIdx.x * blockDim.x + threadIdx.x;
    if (e >= NE) return;
    int r = ei[e];
    int c = ei[NE + e];
    float we = w[e];
    atomicAdd(&g_deg_out[r], we);
    atomicAdd(&g_deg_in[c], we);
}

// ---------------------------------------------------------------- edge aggregation
// thread per EDGE: pf(x)[col] += x[row]/deg_out[row]; pb(x)[row] += x[col]/deg_in[row]
// (reference indexes deg_in by ROW — quirk kept)
__global__ void k_agg(const int* __restrict__ ei, const float* __restrict__ x) {
    int e = blockIdx.x * blockDim.x + threadIdx.x;
    if (e >= NE) return;
    int r = ei[e];
    int c = ei[NE + e];
    float inv_do = __fdividef(1.f, g_deg_out[r]);
    float inv_di = __fdividef(1.f, g_deg_in[r]);
    const float4* xr = (const float4*)(x + r * 8);
    const float4* xc = (const float4*)(x + c * 8);
    float4 a0 = xr[0], a1 = xr[1];
    float4 b0 = xc[0], b1 = xc[1];
    red4(&g_pfx[c * 8],     inv_do * a0.x, inv_do * a0.y, inv_do * a0.z, inv_do * a0.w);
    red4(&g_pfx[c * 8 + 4], inv_do * a1.x, inv_do * a1.y, inv_do * a1.z, inv_do * a1.w);
    red4(&g_pbx[r * 8],     inv_di * b0.x, inv_di * b0.y, inv_di * b0.z, inv_di * b0.w);
    red4(&g_pbx[r * 8 + 4], inv_di * b1.x, inv_di * b1.y, inv_di * b1.z, inv_di * b1.w);
}

// ---------------------------------------------------------------- per-node GRU + A/B
// 4 nodes / 128-thread block, grid=256. Weights staged in smem. b1 folded into g_A.
__global__ void __launch_bounds__(128)
k_node(const float* __restrict__ x,
       const float* __restrict__ Wz, const float* __restrict__ bz,
       const float* __restrict__ Wh, const float* __restrict__ bh,
       const float* __restrict__ w1, const float* __restrict__ b1) {
    __shared__ float swz0[8][32], swz1[8][32], swz2[8][32];
    __shared__ float swh0[8][32], swh1[8][32], swh2[8][32];
    __shared__ float sw1s[80][5];
    __shared__ float so[4][33];

    int t = threadIdx.x;
    for (int idx = t; idx < 256; idx += 128) {
        int k = idx >> 5, c = idx & 31, o = k * 32 + c;
        swz0[k][c] = __ldg(Wz + o) + __ldg(Wz + 2560 + o);
        swz1[k][c] = __ldg(Wz + 1280 + o);
        swz2[k][c] = __ldg(Wz + 3840 + o);
        swh0[k][c] = __ldg(Wh + o) + __ldg(Wh + 2560 + o);
        swh1[k][c] = __ldg(Wh + 1280 + o);
        swh2[k][c] = __ldg(Wh + 3840 + o);
    }
    for (int idx = t; idx < 400; idx += 128)
        sw1s[idx / 5][idx % 5] = __ldg(w1 + idx);
    __syncthreads();

    int wid = t >> 5, lane = t & 31;
    int n = blockIdx.x * 4 + wid;
    const int c = lane;

    float xv[8], pf[8], pb[8];
#pragma unroll
    for (int k = 0; k < 8; k++) {
        xv[k] = __ldg(x + n * 8 + k);
        pf[k] = g_pfx[n * 8 + k];
        pb[k] = g_pbx[n * 8 + k];
    }

    float z = __ldg(bz + c);
    float h = __ldg(bh + c);
#pragma unroll
    for (int k = 0; k < 8; k++) {
        z += xv[k] * swz0[k][c] + pf[k] * swz1[k][c] + pb[k] * swz2[k][c];
        h += xv[k] * swh0[k][c] + pf[k] * swh1[k][c] + pb[k] * swh2[k][c];
    }
    float sig = 1.f / (1.f + __expf(-z));
    float Hn  = (1.f - sig) * tanhf(h);
    so[wid][c] = fmaxf(Hn, 0.f);
    __syncwarp();

    if (lane < 10) {
        int half = lane / 5;           // 0 -> A (w1 rows 0..39), 1 -> B (rows 40..79)
        int m    = lane - half * 5;
        int base = half * 40;
        float acc = (half == 0) ? __ldg(b1 + m) : 0.f;   // fold b1 into A
#pragma unroll
        for (int cc = 0; cc < 32; cc++)
            acc += so[wid][cc] * sw1s[base + cc][m];
#pragma unroll
        for (int k = 0; k < 8; k++)
            acc += xv[k] * sw1s[base + 32 + k][m];
        if (half == 0) g_A[n * 5 + m] = acc;
        else           g_B[n * 5 + m] = acc;
    }
}

// ---------------------------------------------------------------- pair MLP
// 1024 pairs/block (512 threads x 2, stride 512). Because pblk = b*1024 =
// b*1023 + b, we get i0 = kb = b and the block's j-set spans ALL nodes, so the
// ENTIRE g_B table (20KB) is staged with pure float4 copies — no window math.
__global__ void __launch_bounds__(512)
k_pairs(const float* __restrict__ dist, const float* __restrict__ lags,
        const float* __restrict__ lz_,  const float* __restrict__ a2d,
        const float* __restrict__ a2o,  const float* __restrict__ d2a,
        const float* __restrict__ o2a,  const float* __restrict__ vr,
        const float* __restrict__ w1,   const float* __restrict__ w2,
        const float* __restrict__ b2,   const float* __restrict__ w3,
        const float* __restrict__ b3,   const float* __restrict__ w4,
        const float* __restrict__ b4,   float* __restrict__ out) {
    __shared__ float4 sW1[5][3];   // [m]: {wd,wd2,wlg,wz0} {wtd,wto,wda,woa} {wvv,-,-,-}
    __shared__ float4 sW2[3][2];   // [q]: {m0..m3}, {m4, b2q, -, -}
    __shared__ float4 sW3v;        // {w3[0], w3[1], w3[2], b3}
    __shared__ float4 sW4v;        // {w4[0], w4[0]+w4[1], b4, -}
    __shared__ float  sA5[2][5];
    __shared__ __align__(16) float sB[NN * 5];   // full B table (20KB)

    const int b   = blockIdx.x;
    const int pblk = b * PAIRS_PER_BLK;
    const int i0  = b;             // pblk / 1023 == b, pblk % 1023 == b
    int t = threadIdx.x;
    const int p0 = pblk + t;

    // ---- issue stream loads for BOTH pairs immediately (MLP=16) ----
    float dS[2], lgS[2], z0S[2], tdS[2], toS[2], daS[2], oaS[2], vvS[2];
#pragma unroll
    for (int r = 0; r < 2; r++) {
        int p = p0 + r * 512;
        dS[r]  = __ldg(dist + p);
        lgS[r] = __ldg(lags + p);
        z0S[r] = __ldg(lz_  + p);
        tdS[r] = __ldg(a2d  + p);
        toS[r] = __ldg(a2o  + p);
        daS[r] = __ldg(d2a  + p);
        oaS[r] = __ldg(o2a  + p);
        vvS[r] = __ldg(vr   + p);
    }

    // tail-zero scratch for next launch (dead by this point): 18432 floats
    {
        int zi = b * 512 + t;
        if (zi < NN / 2) ((float2*)g_deg_out)[zi] = make_float2(0.f, 0.f);
        else if (zi < NN) ((float2*)g_deg_in)[zi - NN / 2] = make_float2(0.f, 0.f);
        else if (zi < NN + NN * CI / 4)
            ((float4*)g_pfx)[zi - NN] = make_float4(0.f, 0.f, 0.f, 0.f);
        else if (zi < NN + NN * CI / 2)
            ((float4*)g_pbx)[zi - NN - NN * CI / 4] = make_float4(0.f, 0.f, 0.f, 0.f);
    }

    // stage packed weights
    if (t < 15) {                              // sW1: m = t/3, part = t%3
        int m = t / 3, part = t - m * 3;
        int f = part * 4;
        float a0 = w1[400 + f * 5 + m];
        float a1 = (part < 2) ? w1[400 + (f + 1) * 5 + m] : 0.f;
        float a2 = (part < 2) ? w1[400 + (f + 2) * 5 + m] : 0.f;
        float a3 = (part < 2) ? w1[400 + (f + 3) * 5 + m] : 0.f;
        sW1[m][part] = make_float4(a0, a1, a2, a3);
    } else if (t < 21) {                       // sW2: q = (t-15)/2, part = (t-15)%2
        int idx = t - 15, q = idx / 2, part = idx - q * 2;
        if (part == 0)
            sW2[q][0] = make_float4(w2[0 * 3 + q], w2[1 * 3 + q], w2[2 * 3 + q], w2[3 * 3 + q]);
        else
            sW2[q][1] = make_float4(w2[4 * 3 + q], b2[q], 0.f, 0.f);
    } else if (t == 21) {
        sW3v = make_float4(w3[0], w3[1], w3[2], b3[0]);
    } else if (t == 22) {
        float a = w4[0];
        sW4v = make_float4(a, a + w4[1], b4[0], 0.f);
    } else if (t >= 32 && t < 42) {            // stage A rows i0, i0+1 (b1 folded in)
        int q = t - 32, ia = q / 5, m = q - ia * 5;
        sA5[ia][m] = g_A[(i0 + ia) * 5 + m];   // i0+1 <= 1023, in range
    }
    // stage FULL B table: 5120 floats = 1280 float4, pure vector copy
#pragma unroll
    for (int idx = t; idx < 1280; idx += 512)
        ((float4*)sB)[idx] = ((const float4*)g_B)[idx];
    __syncthreads();

#pragma unroll
    for (int r = 0; r < 2; r++) {
        // i, k for this pair (exactly one wrap across the block's k-range)
        int k = b + t + r * 512;
        int i = i0;
        if (k >= NM1) { k -= NM1; i = i0 + 1; }
        int j = (k < i) ? k : (k + 1);

        const float* Bp = sB + j * 5;
        const float* Ap = sA5[i - i0];
        float d = dS[r], d2 = d * d;

        float h1[5];
#pragma unroll
        for (int m = 0; m < 5; m++) {
            float4 wa = sW1[m][0], wb = sW1[m][1], wc = sW1[m][2];
            float v = Ap[m] + Bp[m];
            v += d     * wa.x + d2    * wa.y + lgS[r] * wa.z + z0S[r] * wa.w;
            v += tdS[r]* wb.x + toS[r]* wb.y + daS[r] * wb.z + oaS[r] * wb.w;
            v += vvS[r]* wc.x;
            h1[m] = fmaxf(v, 0.f);
        }
        float h2[3];
#pragma unroll
        for (int q = 0; q < 3; q++) {
            float4 u = sW2[q][0], u2 = sW2[q][1];
            float v = u2.y + h1[0] * u.x + h1[1] * u.y + h1[2] * u.z + h1[3] * u.w + h1[4] * u2.x;
            h2[q] = fmaxf(v, 0.f);
        }
        float4 w3v = sW3v;
        float h3 = w3v.w + h2[0] * w3v.x + h2[1] * w3v.y + h2[2] * w3v.z;
        float4 w4v = sW4v;
        // lag_zeros is exactly 0.0 or 1.0 (round of uniform)
        float w4eff = (z0S[r] != 0.f) ? w4v.y : w4v.x;
        out[p0 + r * 512] = h3 * w4eff + w4v.z;
    }
}

// ---------------------------------------------------------------- launch
extern "C" void kernel_launch(void* const* d_in, const int* in_sizes, int n_in,
                              void* d_out, int out_size) {
    const float* x    = (const float*)d_in[0];
    const int*   ei   = (const int*)  d_in[1];
    const float* ew   = (const float*)d_in[2];
    const float* dist = (const float*)d_in[3];
    const float* lags = (const float*)d_in[4];
    const float* lz   = (const float*)d_in[5];
    const float* a2d  = (const float*)d_in[6];
    const float* a2o  = (const float*)d_in[7];
    const float* d2a  = (const float*)d_in[8];
    const float* o2a  = (const float*)d_in[9];
    const float* vr   = (const float*)d_in[10];
    const float* Wz   = (const float*)d_in[11];
    const float* bz   = (const float*)d_in[12];
    // d_in[13], d_in[14] = Wr, br — dead (H0 == 0 makes the reset gate a no-op)
    const float* Wh   = (const float*)d_in[15];
    const float* bh   = (const float*)d_in[16];
    const float* w1   = (const float*)d_in[17];
    const float* b1   = (const float*)d_in[18];
    const float* w2   = (const float*)d_in[19];
    const float* b2   = (const float*)d_in[20];
    const float* w3   = (const float*)d_in[21];
    const float* b3   = (const float*)d_in[22];
    const float* w4   = (const float*)d_in[23];
    const float* b4   = (const float*)d_in[24];
    float* out = (float*)d_out;

    k_deg<<<(NE + 255) / 256, 256>>>(ei, ew);
    k_agg<<<(NE + 255) / 256, 256>>>(ei, x);
    k_node<<<NN / 4, 128>>>(x, Wz, bz, Wh, bh, w1, b1);
    k_pairs<<<NBLK_PAIRS, 512>>>(dist, lags, lz, a2d, a2o, d2a, o2a, vr,
                                 w1, w2, b2, w3, b3, w4, b4, out);
}